// round 17
// baseline (speedup 1.0000x reference)
#include <cuda_runtime.h>
#include <cuda_fp16.h>
#include <cstdint>

#define NTOK 32768
#define EMB  1024
#define NQKV 3072
#define NH   16
#define HD   64

// ---------------- device scratch (no cudaMalloc allowed) ----------------
__device__ __half g_h  [(size_t)NTOK * EMB];   //  64 MB
__device__ __half g_w  [(size_t)NQKV * EMB];   //   6 MB
__device__ __half g_qkv[(size_t)NTOK * NQKV];  // 192 MB

// ---------------- small PTX helpers (sm_80-baseline only) ----------------
__device__ __forceinline__ uint32_t s2u(const void* p) {
    uint32_t a;
    asm("{ .reg .u64 t; cvta.to.shared.u64 t, %1; cvt.u32.u64 %0, t; }" : "=r"(a) : "l"(p));
    return a;
}

__device__ __forceinline__ void cp16(uint32_t dst, const void* src) {
    asm volatile("cp.async.cg.shared.global [%0], [%1], 16;" :: "r"(dst), "l"(src));
}
#define CP_COMMIT() asm volatile("cp.async.commit_group;" ::: "memory")
#define CP_WAIT0()  asm volatile("cp.async.wait_group 0;" ::: "memory")

__device__ __forceinline__ void ldsm4(uint32_t& r0, uint32_t& r1, uint32_t& r2, uint32_t& r3,
                                      uint32_t addr) {
    asm volatile("ldmatrix.sync.aligned.m8n8.x4.shared.b16 {%0,%1,%2,%3}, [%4];"
                 : "=r"(r0), "=r"(r1), "=r"(r2), "=r"(r3) : "r"(addr));
}

__device__ __forceinline__ void mma16816(float* c, const uint32_t* a, uint32_t b0, uint32_t b1) {
    asm volatile(
        "mma.sync.aligned.m16n8k16.row.col.f32.f16.f16.f32 "
        "{%0,%1,%2,%3}, {%4,%5,%6,%7}, {%8,%9}, {%0,%1,%2,%3};"
        : "+f"(c[0]), "+f"(c[1]), "+f"(c[2]), "+f"(c[3])
        : "r"(a[0]), "r"(a[1]), "r"(a[2]), "r"(a[3]), "r"(b0), "r"(b1));
}

__device__ __forceinline__ float2 h2tof2(uint32_t h) {
    __half2 v = *reinterpret_cast<__half2*>(&h);
    return __half22float2(v);
}

// ---------------- fp32 -> fp16 converts ----------------
__global__ void convert_h_kernel(const float* __restrict__ src) {
    int i4 = blockIdx.x * blockDim.x + threadIdx.x;
    float4 x = reinterpret_cast<const float4*>(src)[i4];
    reinterpret_cast<ushort4*>(g_h)[i4] = make_ushort4(
        __half_as_ushort(__float2half_rn(x.x)), __half_as_ushort(__float2half_rn(x.y)),
        __half_as_ushort(__float2half_rn(x.z)), __half_as_ushort(__float2half_rn(x.w)));
}

__global__ void convert_w_kernel(const float* __restrict__ src) {
    int i4 = blockIdx.x * blockDim.x + threadIdx.x;
    float4 x = reinterpret_cast<const float4*>(src)[i4];
    reinterpret_cast<ushort4*>(g_w)[i4] = make_ushort4(
        __half_as_ushort(__float2half_rn(x.x)), __half_as_ushort(__float2half_rn(x.y)),
        __half_as_ushort(__float2half_rn(x.z)), __half_as_ushort(__float2half_rn(x.w)));
}

// ---------------- QKV GEMM: qkv[m,n] = sum_k h[m,k] * W[n,k] + b[n] ----------------
// BM=128, BN=256, BK=128. 16 warps (512 thr) in 2M x 8N grid, warp tile 64x32.
// 8 k-iterations total: halves per-iteration sync/wait overhead.
// 2-stage cp.async double buffer (209 KB smem), one sync per k-iter.
#define BM 128
#define BN 256
#define BK 128
#define NTT (NQKV / BN)                 // 12
#define SROWB 272                       // 256 B data + 16 B pad per row
#define A_TILE (128 * SROWB)            // 34816 B
#define B_TILE (256 * SROWB)            // 69632 B
#define STAGE_B (A_TILE + B_TILE)       // 104448 B
#define GEMM_SMEM_BYTES (2 * STAGE_B)   // 208896 B

#define O_A 0
#define O_B A_TILE

__device__ __forceinline__ void load_stage(uint32_t sbase, int tid,
                                           const __half* gA, const __half* gB, int kt) {
    int col0 = kt * BK;
    #pragma unroll
    for (int i = 0; i < 4; i++) {           // A: 128 rows x 16 chunks = 2048 / 512 thr
        int idx = tid + i * 512;
        int r = idx >> 4, c = idx & 15;
        uint32_t so = (uint32_t)(r * SROWB + c * 16);
        cp16(sbase + O_A + so, gA + (size_t)r * EMB + col0 + c * 8);
    }
    #pragma unroll
    for (int i = 0; i < 8; i++) {           // B: 256 rows x 16 chunks = 4096 / 512 thr
        int idx = tid + i * 512;
        int r = idx >> 4, c = idx & 15;
        uint32_t so = (uint32_t)(r * SROWB + c * 16);
        cp16(sbase + O_B + so, gB + (size_t)r * EMB + col0 + c * 8);
    }
}

__global__ __launch_bounds__(512, 1) void qkv_gemm_kernel(const float* __restrict__ bias) {
    extern __shared__ char smem[];
    uint32_t base = s2u(smem);
    int tid = threadIdx.x, wid = tid >> 5, lane = tid & 31;
    int mt_blk = blockIdx.x / NTT, nt_blk = blockIdx.x % NTT;
    int mw = wid & 1, nw = wid >> 1;        // 2 x 8 warp grid, warp tile 64x32

    const __half* gA = g_h + (size_t)mt_blk * BM * EMB;
    const __half* gB = g_w + (size_t)nt_blk * BN * EMB;

    int rowA = mw * 64 + (lane & 7) + ((lane >> 3) & 1) * 8;
    int kselA = ((lane >> 4) & 1) * 8;
    int rowB = nw * 32 + (lane & 7) + ((lane >> 4) & 1) * 8;
    int kselB = ((lane >> 3) & 1) * 8;

    float acc[4][4][4];                     // 64 regs
    #pragma unroll
    for (int i = 0; i < 4; i++)
        #pragma unroll
        for (int j = 0; j < 4; j++)
            #pragma unroll
            for (int q = 0; q < 4; q++) acc[i][j][q] = 0.f;

    load_stage(base, tid, gA, gB, 0);
    CP_COMMIT();

    const int KT = EMB / BK;                // 8
    for (int kt = 0; kt < KT; kt++) {
        CP_WAIT0();
        __syncthreads();
        uint32_t sb = base + (uint32_t)(kt & 1) * STAGE_B;

        if (kt + 1 < KT) {
            load_stage(base + (uint32_t)((kt + 1) & 1) * STAGE_B, tid, gA, gB, kt + 1);
            CP_COMMIT();
        }

        #pragma unroll
        for (int ph = 0; ph < 8; ph++) {    // 16-wide k phases within BK=128
            uint32_t ka = (uint32_t)((ph * 16 + kselA) * 2);
            uint32_t kb = (uint32_t)((ph * 16 + kselB) * 2);
            uint32_t ah[4][4];
            #pragma unroll
            for (int t = 0; t < 4; t++) {
                uint32_t ra = (uint32_t)((rowA + t * 16) * SROWB) + ka;
                ldsm4(ah[t][0], ah[t][1], ah[t][2], ah[t][3], sb + O_A + ra);
            }
            #pragma unroll
            for (int p = 0; p < 2; p++) {
                uint32_t bb[4];
                uint32_t rb = (uint32_t)((rowB + p * 16) * SROWB) + kb;
                ldsm4(bb[0], bb[1], bb[2], bb[3], sb + O_B + rb);
                #pragma unroll
                for (int mt = 0; mt < 4; mt++) {
                    #pragma unroll
                    for (int half = 0; half < 2; half++) {
                        int nt = p * 2 + half, o = half * 2;
                        mma16816(acc[mt][nt], ah[mt], bb[o], bb[o + 1]);
                    }
                }
            }
        }
    }

    // epilogue: bias add + fp16 store
    int gid = lane >> 2, tq = lane & 3;
    #pragma unroll
    for (int mt = 0; mt < 4; mt++) {
        int row = mt_blk * BM + mw * 64 + mt * 16 + gid;
        #pragma unroll
        for (int nt = 0; nt < 4; nt++) {
            int col = nt_blk * BN + nw * 32 + nt * 8 + tq * 2;
            float2 bb = *(const float2*)(bias + col);
            *(__half2*)(g_qkv + (size_t)row * NQKV + col) =
                __floats2half2_rn(acc[mt][nt][0] + bb.x, acc[mt][nt][1] + bb.y);
            *(__half2*)(g_qkv + (size_t)(row + 8) * NQKV + col) =
                __floats2half2_rn(acc[mt][nt][2] + bb.x, acc[mt][nt][3] + bb.y);
        }
    }
}

// ---------------- per-token 16x16 head attention + output scatter ----------------
// 256 threads = 4 tokens x 16 heads x 4 slices. fp16 K/V staged in 16KB smem.
// Scores: native half2 HFMA2 dot (fp16 partial acc, fp32 reduce). V: fp32 acc.
__global__ __launch_bounds__(256) void attn_kernel(float* __restrict__ out) {
    __shared__ __half sm[4 * 2048];         // [tok][0:1024)=K, [1024:2048)=V (16 KB)
    int tid = threadIdx.x;
    int n0 = blockIdx.x * 4;
    uint32_t smb = s2u(sm);

    #pragma unroll
    for (int i = 0; i < 4; i++) {
        int id = tid + i * 256;             // 0..1023
        int tok = id >> 8, e = id & 255;
        cp16(smb + (uint32_t)id * 16,
             g_qkv + (size_t)(n0 + tok) * NQKV + 1024 + (size_t)e * 8);
    }
    CP_COMMIT();

    int slice = tid & 3;
    int head  = (tid >> 2) & 15;
    int tok   = tid >> 6;
    int n = n0 + tok;

    __half2 q2[8];
    {
        const uint4* qp = (const uint4*)(g_qkv + (size_t)n * NQKV + head * HD + slice * 16);
        uint4 a = qp[0], b = qp[1];
        uint32_t w[8] = {a.x, a.y, a.z, a.w, b.x, b.y, b.z, b.w};
        #pragma unroll
        for (int t = 0; t < 8; t++) q2[t] = *reinterpret_cast<__half2*>(&w[t]);
    }

    CP_WAIT0();
    __syncthreads();

    const __half* kv = sm + tok * 2048;

    float s[16];
    #pragma unroll
    for (int j = 0; j < 16; j++) {
        const uint4* kp = (const uint4*)(kv + j * HD + slice * 16);
        uint4 a = kp[0], b = kp[1];
        uint32_t w[8] = {a.x, a.y, a.z, a.w, b.x, b.y, b.z, b.w};
        __half2 hacc = __floats2half2_rn(0.f, 0.f);
        #pragma unroll
        for (int t = 0; t < 8; t++)
            hacc = __hfma2(q2[t], *reinterpret_cast<__half2*>(&w[t]), hacc);
        float2 f = __half22float2(hacc);
        float accf = f.x + f.y;
        accf += __shfl_xor_sync(0xffffffffu, accf, 1);
        accf += __shfl_xor_sync(0xffffffffu, accf, 2);
        s[j] = accf * 0.03125f;  // 1/sqrt(1024)
    }

    float mx = s[0];
    #pragma unroll
    for (int j = 1; j < 16; j++) mx = fmaxf(mx, s[j]);
    float sum = 0.f;
    #pragma unroll
    for (int j = 0; j < 16; j++) { s[j] = __expf(s[j] - mx); sum += s[j]; }
    float inv = 1.f / sum;

    float o[16];
    #pragma unroll
    for (int t = 0; t < 16; t++) o[t] = 0.f;
    #pragma unroll
    for (int j = 0; j < 16; j++) {
        float p = s[j] * inv;
        const uint4* vp = (const uint4*)(kv + 1024 + j * HD + slice * 16);
        uint4 a = vp[0], b = vp[1];
        uint32_t w[8] = {a.x, a.y, a.z, a.w, b.x, b.y, b.z, b.w};
        #pragma unroll
        for (int t = 0; t < 8; t++) {
            float2 f = h2tof2(w[t]);
            o[2 * t]     += p * f.x;
            o[2 * t + 1] += p * f.y;
        }
    }

    // out[head*2048 + n/16, (n%16)*64 + slice*16 .. +16)
    float4* dst = (float4*)(out + ((size_t)(head * 2048 + (n >> 4))) * 1024
                                + (n & 15) * 64 + slice * 16);
    #pragma unroll
    for (int t = 0; t < 4; t++)
        dst[t] = make_float4(o[4 * t], o[4 * t + 1], o[4 * t + 2], o[4 * t + 3]);
}

// ---------------- launch ----------------
extern "C" void kernel_launch(void* const* d_in, const int* in_sizes, int n_in,
                              void* d_out, int out_size) {
    const float* h = (const float*)d_in[0];
    const float* W = (const float*)d_in[1];
    const float* b = (const float*)d_in[2];
    float* out = (float*)d_out;

    cudaFuncSetAttribute(qkv_gemm_kernel, cudaFuncAttributeMaxDynamicSharedMemorySize, GEMM_SMEM_BYTES);

    convert_h_kernel<<<32768, 256>>>(h);
    convert_w_kernel<<<3072, 256>>>(W);
    qkv_gemm_kernel<<<(NTOK / BM) * (NQKV / BN), 512, GEMM_SMEM_BYTES>>>(b);  // 3072 CTAs
    attn_kernel<<<NTOK / 4, 256>>>(out);   // 8192 CTAs
}